// round 2
// baseline (speedup 1.0000x reference)
#include <cuda_runtime.h>
#include <math.h>

#define N_NODES  100000
#define N_EDGES  1600000
#define N_GRAPHS 2048

// ---------------- scratch (device globals; no allocations allowed) ----------
__device__ float g_deg [N_NODES];
__device__ float g_dinv[N_NODES];
__device__ float g_norm[N_EDGES];
__device__ float g_A[(size_t)N_NODES * 128];   // GEMM output h (raw)
__device__ float g_B[(size_t)N_NODES * 128];   // aggregation buffer / next-layer input
__device__ float g_pool[N_GRAPHS * 32];
__device__ float g_cnt [N_GRAPHS];

// ---------------- helpers ----------------------------------------------------
__device__ __forceinline__ void red_add_f32x4(float* addr, float4 v) {
    asm volatile("red.global.add.v4.f32 [%0], {%1,%2,%3,%4};"
                 :: "l"(addr), "f"(v.x), "f"(v.y), "f"(v.z), "f"(v.w)
                 : "memory");
}

// ---------------- kernels -----------------------------------------------------

// zero all per-call accumulators + the loss slot of d_out
__global__ void zero_kernel(float* loss_slot) {
    int i = blockIdx.x * blockDim.x + threadIdx.x;
    if (i < N_NODES)        g_deg[i]  = 0.f;
    if (i < N_GRAPHS * 32)  g_pool[i] = 0.f;
    if (i < N_GRAPHS)       g_cnt[i]  = 0.f;
    if (i == 0 && loss_slot) *loss_slot = 0.f;
}

__global__ void degree_kernel(const int* __restrict__ dst) {
    int e = blockIdx.x * blockDim.x + threadIdx.x;
    if (e < N_EDGES) atomicAdd(&g_deg[dst[e]], 1.0f);
}

__global__ void dinv_kernel() {
    int v = blockIdx.x * blockDim.x + threadIdx.x;
    if (v < N_NODES) g_dinv[v] = rsqrtf(g_deg[v] + 1.0f);
}

__global__ void norm_kernel(const int* __restrict__ src, const int* __restrict__ dst) {
    int e = blockIdx.x * blockDim.x + threadIdx.x;
    if (e < N_EDGES) g_norm[e] = g_dinv[src[e]] * g_dinv[dst[e]];
}

// H = (relu?)X @ W  ; AGG = H * dinv^2 + b    (self-loop term + bias fused)
// block = 256 threads, each thread produces 4 output columns.
template<int K, int M, bool RELU_IN>
__global__ void gcn_gemm(const float* __restrict__ X, const float* __restrict__ W,
                         const float* __restrict__ bias,
                         float* __restrict__ H, float* __restrict__ AGG) {
    constexpr int TPR  = M / 4;        // threads per row
    constexpr int ROWS = 256 / TPR;    // rows per block iteration
    constexpr int XSTR = K + 4;        // padded x-row stride (bank-conflict free)
    extern __shared__ float smem[];
    float* Ws = smem;                  // K*M floats
    float* Xs = smem + K * M;          // ROWS * XSTR floats

    for (int i = threadIdx.x; i < K * M / 4; i += 256)
        ((float4*)Ws)[i] = __ldg(((const float4*)W) + i);

    const int r_sub = threadIdx.x / TPR;
    const int c     = threadIdx.x % TPR;

    for (int row0 = blockIdx.x * ROWS; row0 < N_NODES; row0 += gridDim.x * ROWS) {
        __syncthreads();  // Ws ready / previous Xs consumers done
        for (int i = threadIdx.x; i < ROWS * (K / 4); i += 256) {
            int rr = i / (K / 4), kk = i % (K / 4);
            int row = row0 + rr;
            float4 v = make_float4(0.f, 0.f, 0.f, 0.f);
            if (row < N_NODES) {
                v = __ldg(((const float4*)(X + (size_t)row * K)) + kk);
                if (RELU_IN) {
                    v.x = fmaxf(v.x, 0.f); v.y = fmaxf(v.y, 0.f);
                    v.z = fmaxf(v.z, 0.f); v.w = fmaxf(v.w, 0.f);
                }
            }
            *(float4*)(Xs + rr * XSTR + kk * 4) = v;
        }
        __syncthreads();

        int row = row0 + r_sub;
        if (row < N_NODES) {
            float4 acc = make_float4(0.f, 0.f, 0.f, 0.f);
            #pragma unroll 8
            for (int k = 0; k < K; k++) {
                float  xv = Xs[r_sub * XSTR + k];
                float4 wv = *(const float4*)(Ws + k * M + c * 4);
                acc.x = fmaf(xv, wv.x, acc.x);
                acc.y = fmaf(xv, wv.y, acc.y);
                acc.z = fmaf(xv, wv.z, acc.z);
                acc.w = fmaf(xv, wv.w, acc.w);
            }
            float di = g_dinv[row], d2 = di * di;
            float4 bb = __ldg(((const float4*)bias) + c);
            *(float4*)(H   + (size_t)row * M + c * 4) = acc;
            float4 ini = make_float4(fmaf(acc.x, d2, bb.x), fmaf(acc.y, d2, bb.y),
                                     fmaf(acc.z, d2, bb.z), fmaf(acc.w, d2, bb.w));
            *(float4*)(AGG + (size_t)row * M + c * 4) = ini;
        }
    }
}

// AGG[dst] += h[src] * norm[e]   (vector reductions, F/4 threads per edge)
template<int F>
__global__ void edge_scatter(const float* __restrict__ h,
                             const int* __restrict__ src, const int* __restrict__ dst,
                             float* __restrict__ agg) {
    constexpr int TPE = F / 4;
    unsigned gid = blockIdx.x * blockDim.x + threadIdx.x;
    unsigned e = gid / TPE;
    if (e >= N_EDGES) return;
    unsigned c = gid % TPE;
    int s = __ldg(&src[e]);
    int d = __ldg(&dst[e]);
    float nrm = __ldg(&g_norm[e]);
    float4 v = __ldg((const float4*)(h + (size_t)s * F) + c);
    v.x *= nrm; v.y *= nrm; v.z *= nrm; v.w *= nrm;
    red_add_f32x4(agg + (size_t)d * F + c * 4, v);
}

// pooled sums + counts (F = 32 final features, 8 threads/node)
__global__ void pool_kernel(const float* __restrict__ h, const int* __restrict__ batch) {
    unsigned gid = blockIdx.x * blockDim.x + threadIdx.x;
    unsigned v = gid / 8;
    if (v >= N_NODES) return;
    unsigned c = gid % 8;
    int g = __ldg(&batch[v]);
    float4 val = __ldg((const float4*)(h + (size_t)v * 32) + c);
    red_add_f32x4(&g_pool[g * 32 + c * 4], val);
    if (c == 0) atomicAdd(&g_cnt[g], 1.0f);
}

// logits, sigmoid, BCE-with-logits mean loss
__global__ void head_kernel(const float* __restrict__ Wl, const float* __restrict__ bl,
                            const int* __restrict__ targets,
                            float* __restrict__ out, int out_size) {
    int g = blockIdx.x * blockDim.x + threadIdx.x;
    float loss = 0.f;
    if (g < N_GRAPHS) {
        float inv = 1.0f / fmaxf(g_cnt[g], 1.0f);
        float acc = 0.f;
        #pragma unroll
        for (int j = 0; j < 32; j++)
            acc += g_pool[g * 32 + j] * inv * __ldg(&Wl[j]);
        float l = acc + __ldg(&bl[0]);
        out[g] = 1.0f / (1.0f + expf(-l));
        float y = (float)__ldg(&targets[g]);
        loss = fmaxf(l, 0.f) - l * y + log1pf(expf(-fabsf(l)));
    }
    __shared__ float red[256];
    red[threadIdx.x] = loss;
    __syncthreads();
    for (int s = 128; s > 0; s >>= 1) {
        if (threadIdx.x < s) red[threadIdx.x] += red[threadIdx.x + s];
        __syncthreads();
    }
    if (threadIdx.x == 0 && out_size > N_GRAPHS)
        atomicAdd(&out[N_GRAPHS], red[0] * (1.0f / N_GRAPHS));
}

// ---------------- launch ------------------------------------------------------
extern "C" void kernel_launch(void* const* d_in, const int* in_sizes, int n_in,
                              void* d_out, int out_size) {
    const float* x       = (const float*)d_in[0];
    const int*   eidx    = (const int*)  d_in[1];
    const int*   batch   = (const int*)  d_in[2];
    const int*   targets = (const int*)  d_in[3];
    const float* W1 = (const float*)d_in[4];
    const float* b1 = (const float*)d_in[5];
    const float* W2 = (const float*)d_in[6];
    const float* b2 = (const float*)d_in[7];
    const float* W3 = (const float*)d_in[8];
    const float* b3 = (const float*)d_in[9];
    const float* Wl = (const float*)d_in[10];
    const float* bl = (const float*)d_in[11];
    float* out = (float*)d_out;

    const int* src = eidx;
    const int* dst = eidx + N_EDGES;

    float* A;    cudaGetSymbolAddress((void**)&A,    g_A);
    float* B;    cudaGetSymbolAddress((void**)&B,    g_B);

    // dynamic-smem opt-in (layer-1 GEMM needs ~70 KB)
    static bool attr_done = false;
    if (!attr_done) {
        cudaFuncSetAttribute(gcn_gemm<128,128,false>,
                             cudaFuncAttributeMaxDynamicSharedMemorySize, 128*128*4 + 8*132*4);
        cudaFuncSetAttribute(gcn_gemm<128,64,true>,
                             cudaFuncAttributeMaxDynamicSharedMemorySize, 128*64*4 + 16*132*4);
        cudaFuncSetAttribute(gcn_gemm<64,32,true>,
                             cudaFuncAttributeMaxDynamicSharedMemorySize, 64*32*4 + 32*68*4);
        attr_done = true;
    }

    float* loss_slot = (out_size > N_GRAPHS) ? (out + N_GRAPHS) : nullptr;
    zero_kernel<<<(N_NODES + 255) / 256, 256>>>(loss_slot);
    degree_kernel<<<(N_EDGES + 255) / 256, 256>>>(dst);
    dinv_kernel<<<(N_NODES + 255) / 256, 256>>>();
    norm_kernel<<<(N_EDGES + 255) / 256, 256>>>(src, dst);

    // ---- layer 1: 128 -> 128
    {
        int smem = 128*128*4 + 8*132*4;
        gcn_gemm<128,128,false><<<444, 256, smem>>>(x, W1, b1, A, B);
        unsigned total = (unsigned)N_EDGES * 32;
        edge_scatter<128><<<(total + 255) / 256, 256>>>(A, src, dst, B);
    }
    // ---- layer 2: 128 -> 64 (relu on input)
    {
        int smem = 128*64*4 + 16*132*4;
        gcn_gemm<128,64,true><<<592, 256, smem>>>(B, W2, b2, A, B /*overwritten below*/);
        // NOTE: gemm writes AGG into B directly; but B is also its input.
        // Input rows are fully staged into smem before the epilogue writes the
        // same rows, and each row is handled by exactly one block, so in-place
        // is safe per-row (write happens after that row's reads).
        unsigned total = (unsigned)N_EDGES * 16;
        edge_scatter<64><<<(total + 255) / 256, 256>>>(A, src, dst, B);
    }
    // ---- layer 3: 64 -> 32 (relu on input, no relu on output)
    {
        int smem = 64*32*4 + 32*68*4;
        gcn_gemm<64,32,true><<<592, 256, smem>>>(B, W3, b3, A, B);
        unsigned total = (unsigned)N_EDGES * 8;
        edge_scatter<32><<<(total + 255) / 256, 256>>>(A, src, dst, B);
    }

    // ---- pooling + head
    {
        unsigned total = (unsigned)N_NODES * 8;
        pool_kernel<<<(total + 255) / 256, 256>>>(B, batch);
        head_kernel<<<(N_GRAPHS + 255) / 256, 256>>>(Wl, bl, targets, out, out_size);
    }
}

// round 3
// speedup vs baseline: 2.0743x; 2.0743x over previous
#include <cuda_runtime.h>
#include <math.h>

#define N_NODES  100000
#define N_EDGES  1600000
#define N_GRAPHS 2048
#define SCAN_B   1024
#define N_SCAN_BLOCKS ((N_NODES + SCAN_B - 1) / SCAN_B)

// ---------------- scratch (device globals; no allocations allowed) ----------
__device__ int   g_cnt_i[N_NODES];          // per-node incoming-edge count
__device__ int   g_bsum[N_SCAN_BLOCKS];
__device__ int   g_rowptr[N_NODES + 1];
__device__ int   g_cursor[N_NODES];
__device__ int   g_srcs[N_EDGES];           // src ids grouped by dst (CSR)
__device__ float g_dinv[N_NODES];
__device__ float g_A[(size_t)N_NODES * 128];   // h_scaled = (X@W) * dinv[row]
__device__ float g_B[(size_t)N_NODES * 128];   // aggregated output / next input
__device__ float g_pool[N_GRAPHS * 32];
__device__ float g_cntg[N_GRAPHS];

// ---------------- helpers ----------------------------------------------------
__device__ __forceinline__ unsigned long long splat2(float x) {
    unsigned long long r;
    asm("mov.b64 %0, {%1, %1};" : "=l"(r) : "f"(x));
    return r;
}
__device__ __forceinline__ void fma2(unsigned long long& d,
                                     unsigned long long a, unsigned long long b) {
    asm("fma.rn.f32x2 %0, %1, %2, %0;" : "+l"(d) : "l"(a), "l"(b));
}
__device__ __forceinline__ void red_add_f32x4(float* addr, float4 v) {
    asm volatile("red.global.add.v4.f32 [%0], {%1,%2,%3,%4};"
                 :: "l"(addr), "f"(v.x), "f"(v.y), "f"(v.z), "f"(v.w)
                 : "memory");
}

// ---------------- setup kernels -----------------------------------------------
__global__ void zero_kernel(float* loss_slot) {
    int i = blockIdx.x * blockDim.x + threadIdx.x;
    if (i < N_NODES)       g_cnt_i[i] = 0;
    if (i < N_GRAPHS * 32) g_pool[i]  = 0.f;
    if (i < N_GRAPHS)      g_cntg[i]  = 0.f;
    if (i == 0 && loss_slot) *loss_slot = 0.f;
}

__global__ void hist_kernel(const int* __restrict__ dst) {
    int e = blockIdx.x * blockDim.x + threadIdx.x;
    if (e < N_EDGES) atomicAdd(&g_cnt_i[dst[e]], 1);
}

__global__ void scan_local() {
    __shared__ int sm[SCAN_B];
    int gi = blockIdx.x * SCAN_B + threadIdx.x;
    int v = (gi < N_NODES) ? g_cnt_i[gi] : 0;
    int val = v;
    sm[threadIdx.x] = val;
    __syncthreads();
    for (int off = 1; off < SCAN_B; off <<= 1) {
        int t = (threadIdx.x >= off) ? sm[threadIdx.x - off] : 0;
        __syncthreads();
        val += t;
        sm[threadIdx.x] = val;
        __syncthreads();
    }
    if (gi < N_NODES) g_rowptr[gi] = val - v;          // block-local exclusive
    if (threadIdx.x == SCAN_B - 1) g_bsum[blockIdx.x] = val;
}

__global__ void scan_block() {
    __shared__ int sm[128];
    int t = threadIdx.x;
    int v = (t < N_SCAN_BLOCKS) ? g_bsum[t] : 0;
    int val = v;
    sm[t] = val;
    __syncthreads();
    for (int off = 1; off < 128; off <<= 1) {
        int u = (t >= off) ? sm[t - off] : 0;
        __syncthreads();
        val += u;
        sm[t] = val;
        __syncthreads();
    }
    if (t < N_SCAN_BLOCKS) g_bsum[t] = val - v;        // exclusive
}

__global__ void scan_add() {
    int i = blockIdx.x * blockDim.x + threadIdx.x;
    if (i < N_NODES) {
        int ex = g_rowptr[i] + g_bsum[i / SCAN_B];
        g_rowptr[i] = ex;
        g_cursor[i] = ex;
        g_dinv[i]   = rsqrtf((float)g_cnt_i[i] + 1.0f);
    }
    if (i == 0) g_rowptr[N_NODES] = N_EDGES;
}

__global__ void fill_csr(const int* __restrict__ src, const int* __restrict__ dst) {
    int e = blockIdx.x * blockDim.x + threadIdx.x;
    if (e < N_EDGES) {
        int p = atomicAdd(&g_cursor[dst[e]], 1);
        g_srcs[p] = src[e];
    }
}

// ---------------- GEMM: HS = ((relu?)X @ W) * dinv[row] -----------------------
// 256 threads; each thread: 4 rows x 4 cols, packed f32x2 FMA.
template<int K, int M, bool RELU_IN>
__global__ void gcn_gemm(const float* __restrict__ X, const float* __restrict__ W,
                         float* __restrict__ HS) {
    constexpr int TPR  = M / 4;               // threads covering one row's cols
    constexpr int RPT  = 4;                   // rows per thread
    constexpr int ROWS = (256 / TPR) * RPT;   // rows per tile
    constexpr int XSTR = K + 4;               // padded row stride (16B-safe: K%4==0)
    extern __shared__ float smem[];
    float* Ws = smem;                         // K*M
    float* Xs = smem + K * M;                 // ROWS*XSTR

    for (int i = threadIdx.x; i < K * M / 4; i += 256)
        ((float4*)Ws)[i] = __ldg((const float4*)W + i);

    const int rg = (threadIdx.x / TPR) * RPT;
    const int c  = threadIdx.x % TPR;

    for (int row0 = blockIdx.x * ROWS; row0 < N_NODES; row0 += gridDim.x * ROWS) {
        __syncthreads();
        for (int i = threadIdx.x; i < ROWS * (K / 4); i += 256) {
            int rr = i / (K / 4), kk = i % (K / 4);
            int row = row0 + rr;
            float4 v = make_float4(0.f, 0.f, 0.f, 0.f);
            if (row < N_NODES) {
                v = __ldg((const float4*)(X + (size_t)row * K) + kk);
                if (RELU_IN) {
                    v.x = fmaxf(v.x, 0.f); v.y = fmaxf(v.y, 0.f);
                    v.z = fmaxf(v.z, 0.f); v.w = fmaxf(v.w, 0.f);
                }
            }
            *(float4*)(Xs + rr * XSTR + kk * 4) = v;
        }
        __syncthreads();

        unsigned long long a0[RPT], a1[RPT];
        #pragma unroll
        for (int j = 0; j < RPT; j++) { a0[j] = 0ull; a1[j] = 0ull; }

        #pragma unroll 2
        for (int k = 0; k < K; k += 4) {
            float4 xv[RPT];
            #pragma unroll
            for (int j = 0; j < RPT; j++)
                xv[j] = *(const float4*)(Xs + (rg + j) * XSTR + k);
            #pragma unroll
            for (int kk = 0; kk < 4; kk++) {
                ulonglong2 w = *(const ulonglong2*)(Ws + (k + kk) * M + c * 4);
                #pragma unroll
                for (int j = 0; j < RPT; j++) {
                    float xf = (kk == 0) ? xv[j].x : (kk == 1) ? xv[j].y
                             : (kk == 2) ? xv[j].z : xv[j].w;
                    unsigned long long xx = splat2(xf);
                    fma2(a0[j], xx, w.x);
                    fma2(a1[j], xx, w.y);
                }
            }
        }

        #pragma unroll
        for (int j = 0; j < RPT; j++) {
            int row = row0 + rg + j;
            if (row < N_NODES) {
                float di = g_dinv[row];
                float2 p0 = *(float2*)&a0[j];
                float2 p1 = *(float2*)&a1[j];
                float4 o = make_float4(p0.x * di, p0.y * di, p1.x * di, p1.y * di);
                *(float4*)(HS + (size_t)row * M + c * 4) = o;
            }
        }
    }
}

// ---------------- aggregation: OUT[v] = dinv[v]*(sum_in HS[s] + HS[v]) + b ----
template<int F>
__global__ void agg_gather(const float* __restrict__ HS, const float* __restrict__ bias,
                           float* __restrict__ OUT) {
    constexpr int TPN = F / 4;
    unsigned gid = blockIdx.x * blockDim.x + threadIdx.x;
    unsigned v = gid / TPN;
    if (v >= N_NODES) return;
    unsigned c = gid % TPN;
    const float4* hs = (const float4*)HS;

    int beg = __ldg(&g_rowptr[v]);
    int end = __ldg(&g_rowptr[v + 1]);

    float4 acc0 = __ldg(hs + (size_t)v * TPN + c);       // self-loop term
    float4 acc1 = make_float4(0.f, 0.f, 0.f, 0.f);

    int i = beg;
    for (; i + 1 < end; i += 2) {
        int s0 = __ldg(&g_srcs[i]);
        int s1 = __ldg(&g_srcs[i + 1]);
        float4 m0 = __ldg(hs + (size_t)s0 * TPN + c);
        float4 m1 = __ldg(hs + (size_t)s1 * TPN + c);
        acc0.x += m0.x; acc0.y += m0.y; acc0.z += m0.z; acc0.w += m0.w;
        acc1.x += m1.x; acc1.y += m1.y; acc1.z += m1.z; acc1.w += m1.w;
    }
    if (i < end) {
        int s = __ldg(&g_srcs[i]);
        float4 m = __ldg(hs + (size_t)s * TPN + c);
        acc0.x += m.x; acc0.y += m.y; acc0.z += m.z; acc0.w += m.w;
    }

    float di = g_dinv[v];
    float4 bb = __ldg((const float4*)bias + c);
    float4 o;
    o.x = fmaf(acc0.x + acc1.x, di, bb.x);
    o.y = fmaf(acc0.y + acc1.y, di, bb.y);
    o.z = fmaf(acc0.z + acc1.z, di, bb.z);
    o.w = fmaf(acc0.w + acc1.w, di, bb.w);
    ((float4*)OUT)[(size_t)v * TPN + c] = o;
}

// ---------------- pooling + head ----------------------------------------------
__global__ void pool_kernel(const float* __restrict__ h, const int* __restrict__ batch) {
    unsigned gid = blockIdx.x * blockDim.x + threadIdx.x;
    unsigned v = gid / 8;
    if (v >= N_NODES) return;
    unsigned c = gid % 8;
    int g = __ldg(&batch[v]);
    float4 val = __ldg((const float4*)(h + (size_t)v * 32) + c);
    red_add_f32x4(&g_pool[g * 32 + c * 4], val);
    if (c == 0) atomicAdd(&g_cntg[g], 1.0f);
}

__global__ void head_kernel(const float* __restrict__ Wl, const float* __restrict__ bl,
                            const int* __restrict__ targets,
                            float* __restrict__ out, int out_size) {
    int g = blockIdx.x * blockDim.x + threadIdx.x;
    float loss = 0.f;
    if (g < N_GRAPHS) {
        float inv = 1.0f / fmaxf(g_cntg[g], 1.0f);
        float acc = 0.f;
        #pragma unroll
        for (int j = 0; j < 32; j++)
            acc += g_pool[g * 32 + j] * inv * __ldg(&Wl[j]);
        float l = acc + __ldg(&bl[0]);
        out[g] = 1.0f / (1.0f + expf(-l));
        float y = (float)__ldg(&targets[g]);
        loss = fmaxf(l, 0.f) - l * y + log1pf(expf(-fabsf(l)));
    }
    __shared__ float red[256];
    red[threadIdx.x] = loss;
    __syncthreads();
    for (int s = 128; s > 0; s >>= 1) {
        if (threadIdx.x < s) red[threadIdx.x] += red[threadIdx.x + s];
        __syncthreads();
    }
    if (threadIdx.x == 0 && out_size > N_GRAPHS)
        atomicAdd(&out[N_GRAPHS], red[0] * (1.0f / N_GRAPHS));
}

// ---------------- launch ------------------------------------------------------
extern "C" void kernel_launch(void* const* d_in, const int* in_sizes, int n_in,
                              void* d_out, int out_size) {
    const float* x       = (const float*)d_in[0];
    const int*   eidx    = (const int*)  d_in[1];
    const int*   batch   = (const int*)  d_in[2];
    const int*   targets = (const int*)  d_in[3];
    const float* W1 = (const float*)d_in[4];
    const float* b1 = (const float*)d_in[5];
    const float* W2 = (const float*)d_in[6];
    const float* b2 = (const float*)d_in[7];
    const float* W3 = (const float*)d_in[8];
    const float* b3 = (const float*)d_in[9];
    const float* Wl = (const float*)d_in[10];
    const float* bl = (const float*)d_in[11];
    float* out = (float*)d_out;

    const int* src = eidx;
    const int* dst = eidx + N_EDGES;

    float* A;  cudaGetSymbolAddress((void**)&A, g_A);
    float* B;  cudaGetSymbolAddress((void**)&B, g_B);

    const int smem1 = 128 * 128 * 4 + 32  * 132 * 4;  // 82432
    const int smem2 = 128 * 64  * 4 + 64  * 132 * 4;  // 66560
    const int smem3 = 64  * 32  * 4 + 128 * 68  * 4;  // 43008
    cudaFuncSetAttribute(gcn_gemm<128,128,false>,
                         cudaFuncAttributeMaxDynamicSharedMemorySize, smem1);
    cudaFuncSetAttribute(gcn_gemm<128,64,true>,
                         cudaFuncAttributeMaxDynamicSharedMemorySize, smem2);
    cudaFuncSetAttribute(gcn_gemm<64,32,true>,
                         cudaFuncAttributeMaxDynamicSharedMemorySize, smem3);

    float* loss_slot = (out_size > N_GRAPHS) ? (out + N_GRAPHS) : nullptr;

    zero_kernel<<<(N_NODES + 255) / 256, 256>>>(loss_slot);
    hist_kernel<<<(N_EDGES + 255) / 256, 256>>>(dst);
    scan_local<<<N_SCAN_BLOCKS, SCAN_B>>>();
    scan_block<<<1, 128>>>();
    scan_add<<<(N_NODES + 255) / 256, 256>>>();
    fill_csr<<<(N_EDGES + 255) / 256, 256>>>(src, dst);

    // ---- layer 1: 128 -> 128
    gcn_gemm<128,128,false><<<296, 256, smem1>>>(x, W1, A);
    agg_gather<128><<<((unsigned)N_NODES * 32 + 255) / 256, 256>>>(A, b1, B);
    // ---- layer 2: 128 -> 64 (relu on input)
    gcn_gemm<128,64,true><<<296, 256, smem2>>>(B, W2, A);
    agg_gather<64><<<((unsigned)N_NODES * 16 + 255) / 256, 256>>>(A, b2, B);
    // ---- layer 3: 64 -> 32 (relu on input)
    gcn_gemm<64,32,true><<<296, 256, smem3>>>(B, W3, A);
    agg_gather<32><<<((unsigned)N_NODES * 8 + 255) / 256, 256>>>(A, b3, B);

    // ---- pooling + head
    pool_kernel<<<((unsigned)N_NODES * 8 + 255) / 256, 256>>>(B, batch);
    head_kernel<<<(N_GRAPHS + 255) / 256, 256>>>(Wl, bl, targets, out, out_size);
}